// round 3
// baseline (speedup 1.0000x reference)
#include <cuda_runtime.h>
#include <cstdint>

#define NMAX 50000
#define EMAX 800000
#define DD 64
#define SCAN_B 1024
#define NBLK ((NMAX + SCAN_B - 1) / SCAN_B)   // 49

// ------------------------- scratch (__device__ globals; no allocs) ----------
__device__ int   g_cnt[NMAX];              // in-degree (without self-loop)
__device__ int   g_rs[NMAX];               // CSR row start (exclusive scan of cnt)
__device__ int   g_cur[NMAX];              // placement cursor
__device__ int   g_bsum[NBLK];             // scan block sums
__device__ __align__(16) float g_dinv[NMAX];
__device__ int   g_esrc[EMAX];             // CSR: src node per slot
__device__ float g_enorm[EMAX];            // CSR: dinv[src]*dinv[dst] per slot
__device__ __align__(16) float g_h[NMAX * DD];
__device__ __align__(16) float g_out1[NMAX * DD];
__device__ __align__(16) float g_out2[NMAX * DD];
__device__ __align__(16) float g_out3[NMAX * DD];
__device__ float g_conc[NMAX];
__device__ float g_sum[1];

__device__ __forceinline__ int clampi(int v, int lo, int hi) {
    return v < lo ? lo : (v > hi ? hi : v);
}

// ------------------------- prep ---------------------------------------------
__global__ void k_zero(int n) {
    int i = blockIdx.x * blockDim.x + threadIdx.x;
    if (i < n) g_cnt[i] = 0;
    if (i == 0) g_sum[0] = 0.0f;
}

// edge_index is int32 (JAX x64 disabled): layout [2, E] row-major
__global__ void k_count(const int* __restrict__ ei, int E, int n) {
    int e = blockIdx.x * blockDim.x + threadIdx.x;
    if (e >= E) return;
    int d = clampi(ei[E + e], 0, n - 1);
    atomicAdd(&g_cnt[d], 1);
}

__global__ void k_dinv(int n) {
    int i = blockIdx.x * blockDim.x + threadIdx.x;
    if (i < n) g_dinv[i] = rsqrtf((float)g_cnt[i] + 1.0f);
}

// ---- 3-phase exclusive scan of g_cnt -> g_rs --------------------------------
__global__ void k_scan1(int n) {
    __shared__ int sh[SCAN_B];
    int t = threadIdx.x;
    int i = blockIdx.x * SCAN_B + t;
    int v = (i < n) ? g_cnt[i] : 0;
    sh[t] = v;
    __syncthreads();
    for (int off = 1; off < SCAN_B; off <<= 1) {
        int a = (t >= off) ? sh[t - off] : 0;
        __syncthreads();
        sh[t] += a;
        __syncthreads();
    }
    if (i < n) g_rs[i] = sh[t] - v;              // exclusive within block
    if (t == SCAN_B - 1) g_bsum[blockIdx.x] = sh[t];
}

__global__ void k_scan2(int nb) {
    if (threadIdx.x == 0) {
        int run = 0;
        for (int i = 0; i < nb; i++) { int v = g_bsum[i]; g_bsum[i] = run; run += v; }
    }
}

__global__ void k_scan3(int n) {
    int i = blockIdx.x * SCAN_B + threadIdx.x;
    if (i < n) {
        int v = g_rs[i] + g_bsum[blockIdx.x];
        g_rs[i] = v;
        g_cur[i] = v;
    }
}

// ---- CSR placement: store src + norm per slot -------------------------------
__global__ void k_place(const int* __restrict__ ei, int E, int n) {
    int e = blockIdx.x * blockDim.x + threadIdx.x;
    if (e >= E) return;
    int s = clampi(ei[e], 0, n - 1);
    int d = clampi(ei[E + e], 0, n - 1);
    int pos = atomicAdd(&g_cur[d], 1);
    g_esrc[pos] = s;
    g_enorm[pos] = g_dinv[s] * g_dinv[d];
}

// ------------------------- GEMM: g_h = x @ W ---------------------------------
// 256 threads, 32 rows per block. W (64x64) + x tile (32x64) in smem.
__global__ void k_gemm(const float* __restrict__ xext, int sel,
                       const float* __restrict__ W, int n) {
    __shared__ float Ws[DD * DD];
    __shared__ float xs[32 * DD];
    const float* x = (sel == 0) ? xext : (sel == 1 ? g_out1 : g_out2);

    int tid = threadIdx.x;
    for (int i = tid; i < DD * DD; i += 256) Ws[i] = W[i];

    int row0 = blockIdx.x * 32;
    int nrows = n - row0; if (nrows > 32) nrows = 32;
    for (int i = tid; i < nrows * DD; i += 256) xs[i] = x[row0 * DD + i];
    __syncthreads();

    int c  = tid & 63;
    int r0 = (tid >> 6) * 8;
    float acc[8];
#pragma unroll
    for (int rr = 0; rr < 8; rr++) acc[rr] = 0.0f;

#pragma unroll 8
    for (int k = 0; k < DD; k++) {
        float w = Ws[k * DD + c];
#pragma unroll
        for (int rr = 0; rr < 8; rr++)
            acc[rr] += xs[(r0 + rr) * DD + k] * w;
    }

#pragma unroll
    for (int rr = 0; rr < 8; rr++) {
        int r = row0 + r0 + rr;
        if (r < n) g_h[r * DD + c] = acc[rr];
    }
}

// ---- aggregate: out = relu( sum_in norm*h[src] + h[node]*dinv^2 + b ) -------
// warp per node; lane covers channels lane and lane+32
__global__ void k_agg(const float* __restrict__ b, int sel, int n) {
    int node = (int)((blockIdx.x * (unsigned)blockDim.x + threadIdx.x) >> 5);
    int lane = threadIdx.x & 31;
    if (node >= n) return;

    float di = g_dinv[node];
    float sl = di * di;
    float acc0 = g_h[node * DD + lane]      * sl + b[lane];
    float acc1 = g_h[node * DD + 32 + lane] * sl + b[32 + lane];

    int beg = g_rs[node];
    int end = beg + g_cnt[node];

    int j = beg;
    for (; j + 1 < end; j += 2) {
        int   s0 = g_esrc[j],     s1 = g_esrc[j + 1];
        float n0 = g_enorm[j],    n1 = g_enorm[j + 1];
        float a0 = g_h[s0 * DD + lane];
        float a1 = g_h[s0 * DD + 32 + lane];
        float c0 = g_h[s1 * DD + lane];
        float c1 = g_h[s1 * DD + 32 + lane];
        acc0 += n0 * a0 + n1 * c0;
        acc1 += n0 * a1 + n1 * c1;
    }
    if (j < end) {
        int   s0 = g_esrc[j];
        float n0 = g_enorm[j];
        acc0 += n0 * g_h[s0 * DD + lane];
        acc1 += n0 * g_h[s0 * DD + 32 + lane];
    }

    acc0 = fmaxf(acc0, 0.0f);
    acc1 = fmaxf(acc1, 0.0f);
    float* out = (sel == 1) ? g_out1 : (sel == 2 ? g_out2 : g_out3);
    out[node * DD + lane]      = acc0;
    out[node * DD + 32 + lane] = acc1;
}

// ------------------------- MLP head: warp per node ---------------------------
__global__ void k_mlp(const float* __restrict__ state,
                      const float* __restrict__ lw1, const float* __restrict__ lb1,
                      const float* __restrict__ lw2, const float* __restrict__ lb2,
                      const float* __restrict__ lw3, const float* __restrict__ lb3,
                      int n) {
    __shared__ float s_lw1[256 * 32];
    __shared__ float s_lw2[32 * 32];
    __shared__ float s_lw3[32];
    __shared__ float s_lb1[32];
    __shared__ float s_lb2[32];
    __shared__ float s_blk[8];

    int tid = threadIdx.x;
    for (int i = tid; i < 256 * 32; i += 256) s_lw1[i] = lw1[i];
    for (int i = tid; i < 32 * 32; i += 256)  s_lw2[i] = lw2[i];
    if (tid < 32) { s_lw3[tid] = lw3[tid]; s_lb1[tid] = lb1[tid]; s_lb2[tid] = lb2[tid]; }
    __syncthreads();

    int warp = tid >> 5, lane = tid & 31;
    int node = blockIdx.x * 8 + warp;
    float conc = 0.0f;

    if (node < n) {
        float acc = s_lb1[lane];
        const float* segs[4] = {&g_out1[node * DD], &g_out2[node * DD],
                                &g_out3[node * DD], &state[node * DD]};
#pragma unroll
        for (int sg = 0; sg < 4; sg++) {
            const float* xp = segs[sg];
#pragma unroll
            for (int k0 = 0; k0 < DD; k0 += 32) {
                float xv = xp[k0 + lane];
#pragma unroll
                for (int i = 0; i < 32; i++) {
                    float xsv = __shfl_sync(0xffffffffu, xv, i);
                    acc += xsv * s_lw1[(sg * DD + k0 + i) * 32 + lane];
                }
            }
        }
        float h1 = acc > 0.0f ? acc : 0.01f * acc;     // leaky_relu(0.01)

        float acc2 = s_lb2[lane];
#pragma unroll
        for (int i = 0; i < 32; i++) {
            float hi = __shfl_sync(0xffffffffu, h1, i);
            acc2 += hi * s_lw2[i * 32 + lane];
        }
        float h2 = acc2 > 0.0f ? acc2 : 0.01f * acc2;

        float part = h2 * s_lw3[lane];
#pragma unroll
        for (int off = 16; off > 0; off >>= 1)
            part += __shfl_xor_sync(0xffffffffu, part, off);

        if (lane == 0) {
            float z = part + lb3[0];
            float sp = fmaxf(z, 0.0f) + log1pf(expf(-fabsf(z)));  // stable softplus
            g_conc[node] = sp;
            conc = sp;                                 // sp >= 0 => |sp| == sp
        }
    }

    if (lane == 0) s_blk[warp] = conc;
    __syncthreads();
    if (tid == 0) {
        float s = 0.0f;
#pragma unroll
        for (int i = 0; i < 8; i++) s += s_blk[i];
        atomicAdd(&g_sum[0], s);
    }
}

// ------------------------- final: action + regularize ------------------------
__global__ void k_final(float* __restrict__ out, int n, int out_n) {
    int i = blockIdx.x * blockDim.x + threadIdx.x;
    float s = g_sum[0];
    if (i < n) out[i] = g_conc[i] / (s + 1e-20f);
    if (i == 0 && out_n > n) out[n] = s / (float)n;    // mean(|conc|)
}

// ------------------------- launch --------------------------------------------
extern "C" void kernel_launch(void* const* d_in, const int* in_sizes, int n_in,
                              void* d_out, int out_size) {
    const float* state = (const float*)d_in[0];
    const int*   ei    = (const int*)d_in[1];       // int32 (JAX x64 disabled)
    const float* W1 = (const float*)d_in[2];
    const float* b1 = (const float*)d_in[3];
    const float* W2 = (const float*)d_in[4];
    const float* b2 = (const float*)d_in[5];
    const float* W3 = (const float*)d_in[6];
    const float* b3 = (const float*)d_in[7];
    const float* lw1 = (const float*)d_in[8];
    const float* lb1 = (const float*)d_in[9];
    const float* lw2 = (const float*)d_in[10];
    const float* lb2 = (const float*)d_in[11];
    const float* lw3 = (const float*)d_in[12];
    const float* lb3 = (const float*)d_in[13];

    int n = in_sizes[0] / DD;        // 50000
    int E = in_sizes[1] / 2;         // 800000
    float* out = (float*)d_out;

    int nb_n  = (n + 255) / 256;
    int nb_e  = (E + 255) / 256;
    int nb_sc = (n + SCAN_B - 1) / SCAN_B;
    int nb_g  = (n + 31) / 32;
    int nb_a  = (n * 32 + 255) / 256;   // warp per node, 256 thr/block

    // CSR build
    k_zero <<<nb_n, 256>>>(n);
    k_count<<<nb_e, 256>>>(ei, E, n);
    k_dinv <<<nb_n, 256>>>(n);
    k_scan1<<<nb_sc, SCAN_B>>>(n);
    k_scan2<<<1, 32>>>(nb_sc);
    k_scan3<<<nb_sc, SCAN_B>>>(n);
    k_place<<<nb_e, 256>>>(ei, E, n);

    // layer 1
    k_gemm<<<nb_g, 256>>>(state, 0, W1, n);
    k_agg <<<nb_a, 256>>>(b1, 1, n);
    // layer 2
    k_gemm<<<nb_g, 256>>>(nullptr, 1, W2, n);
    k_agg <<<nb_a, 256>>>(b2, 2, n);
    // layer 3
    k_gemm<<<nb_g, 256>>>(nullptr, 2, W3, n);
    k_agg <<<nb_a, 256>>>(b3, 3, n);

    k_mlp  <<<(n + 7) / 8, 256>>>(state, lw1, lb1, lw2, lb2, lw3, lb3, n);
    k_final<<<nb_n, 256>>>(out, n, out_size);
}